// round 14
// baseline (speedup 1.0000x reference)
#include <cuda_runtime.h>
#include <cuda.h>
#include <cuda_bf16.h>
#include <math.h>
#include <stdint.h>

// ---------------- problem constants ----------------
#define BB_   2
#define TT_   4096
#define DD_   4096
#define HH_   32
#define MM_   (BB_*TT_)          // 8192
#define NQ_   4096
#define NKV_  1024
#define NTOT_ 6144

// ---------------- scratch (device globals; no allocations allowed) --------
__device__ __nv_bfloat16 g_A[(size_t)2 * MM_ * DD_];    // [hi|lo][M][K]
__device__ __nv_bfloat16 g_Bm[(size_t)2 * NTOT_ * DD_]; // [hi|lo][N][K]
__device__ float g_cos[TT_ * 64];
__device__ float g_sin[TT_ * 64];

struct InvFreq { float v[64]; };

// ---------------- PTX helpers (all non-'a'-gated: sm_80/sm_90 ISA) --------
__device__ __forceinline__ uint32_t smem_u32(const void* p) {
    uint32_t a;
    asm("{ .reg .u64 t; cvta.to.shared.u64 t, %1; cvt.u32.u64 %0, t; }"
        : "=r"(a) : "l"(p));
    return a;
}

#define MBAR_INIT(a, c) \
    asm volatile("mbarrier.init.shared.b64 [%0], %1;" :: "r"(a), "r"(c) : "memory")

#define MBAR_ARRIVE(a) \
    asm volatile("mbarrier.arrive.shared.b64 _, [%0];" :: "r"(a) : "memory")

#define MBAR_EXPECT_TX(a, b) \
    asm volatile("mbarrier.arrive.expect_tx.shared.b64 _, [%0], %1;" :: "r"(a), "r"(b) : "memory")

#define MBAR_WAIT(addr, ph) do {                                              \
    uint32_t _m = (addr), _p = (ph), _d;                                      \
    asm volatile("{\n .reg .pred p;\n"                                        \
        " mbarrier.try_wait.parity.acquire.cta.shared::cta.b64 p, [%1], %2;\n"\
        " selp.b32 %0, 1, 0, p;\n}"                                           \
        : "=r"(_d) : "r"(_m), "r"(_p) : "memory");                            \
    if (!_d) {                                                                \
        asm volatile("{\n .reg .pred P1;\n"                                   \
            "WL%=:\n"                                                         \
            " mbarrier.try_wait.parity.acquire.cta.shared::cta.b64 P1, [%0], %1, 0x989680;\n" \
            " @P1 bra.uni WD%=;\n bra.uni WL%=;\nWD%=:\n}"                    \
            :: "r"(_m), "r"(_p) : "memory");                                  \
    } } while (0)

#define TMA_LOAD_3D(smem_addr, tmap, cx, cy, cz, mbar)                        \
    asm volatile(                                                             \
        "cp.async.bulk.tensor.3d.shared::cta.global.tile.mbarrier::complete_tx::bytes " \
        "[%0], [%1, {%2, %3, %4}], [%5];"                                     \
        :: "r"((uint32_t)(smem_addr)), "l"(tmap), "r"((int32_t)(cx)),         \
           "r"((int32_t)(cy)), "r"((int32_t)(cz)), "r"((uint32_t)(mbar))      \
        : "memory")

#define LDSM4(r, addr) \
    asm volatile("ldmatrix.sync.aligned.m8n8.x4.shared.b16 {%0,%1,%2,%3}, [%4];" \
        : "=r"((r)[0]), "=r"((r)[1]), "=r"((r)[2]), "=r"((r)[3]) : "r"(addr))

#define MMA16816(c, a, b0, b1) \
    asm volatile("mma.sync.aligned.m16n8k16.row.col.f32.bf16.bf16.f32 " \
        "{%0,%1,%2,%3}, {%4,%5,%6,%7}, {%8,%9}, {%0,%1,%2,%3};" \
        : "+f"((c)[0]), "+f"((c)[1]), "+f"((c)[2]), "+f"((c)[3]) \
        : "r"((a)[0]), "r"((a)[1]), "r"((a)[2]), "r"((a)[3]), "r"(b0), "r"(b1))

// ---------------------------------------------------------------------------
// Kernel 1 (merged preamble): blocks [0, MM_) do LayerNorm + A split + RoPE
// table; blocks [MM_, MM_+12288) do weight transpose + B split.
// ---------------------------------------------------------------------------
#define WSPLIT_BLOCKS (64 * 192)        // (DD_/64) x (NTOT_/32)

__global__ __launch_bounds__(256) void preamble_kernel(
    const float* __restrict__ x,
    const float* __restrict__ gamma,
    const float* __restrict__ beta,
    const float* __restrict__ Wq,
    const float* __restrict__ Wk,
    const float* __restrict__ Wv,
    const __grid_constant__ InvFreq invf)
{
    __shared__ float tile[64][33];      // wsplit scratch (8.5 KB; ln uses 64B)
    int bid = blockIdx.x;
    int tid = threadIdx.x;

    if (bid >= MM_) {
        // ---------------- wsplit branch ----------------
        int wb = bid - MM_;
        int k0 = (wb & 63) * 64;
        int n0 = (wb >> 6) * 32;

        const float* W; int ld, nb;
        if (n0 < NQ_)            { W = Wq; ld = NQ_;  nb = n0; }
        else if (n0 < NQ_ + NKV_){ W = Wk; ld = NKV_; nb = n0 - NQ_; }
        else                     { W = Wv; ld = NKV_; nb = n0 - NQ_ - NKV_; }

#pragma unroll
        for (int i = 0; i < 8; i++) {
            int e = tid + i * 256;
            int r = e >> 5, c = e & 31;
            tile[r][c] = W[(size_t)(k0 + r) * ld + nb + c];
        }
        __syncthreads();

        __nv_bfloat16* Bhi = g_Bm;
        __nv_bfloat16* Blo = g_Bm + (size_t)NTOT_ * DD_;
        int nl = tid >> 3;
        int kg = (tid & 7) * 8;
        uint32_t hw[4], lw[4];
#pragma unroll
        for (int p = 0; p < 4; p++) {
            float f0 = tile[kg + 2*p + 0][nl];
            float f1 = tile[kg + 2*p + 1][nl];
            __nv_bfloat16 h0 = __float2bfloat16(f0);
            __nv_bfloat16 h1 = __float2bfloat16(f1);
            __nv_bfloat16 l0 = __float2bfloat16(f0 - __bfloat162float(h0));
            __nv_bfloat16 l1 = __float2bfloat16(f1 - __bfloat162float(h1));
            hw[p] = (uint32_t)__bfloat16_as_ushort(h0) | ((uint32_t)__bfloat16_as_ushort(h1) << 16);
            lw[p] = (uint32_t)__bfloat16_as_ushort(l0) | ((uint32_t)__bfloat16_as_ushort(l1) << 16);
        }
        size_t off = (size_t)(n0 + nl) * DD_ + k0 + kg;
        *(uint4*)(Bhi + off) = make_uint4(hw[0], hw[1], hw[2], hw[3]);
        *(uint4*)(Blo + off) = make_uint4(lw[0], lw[1], lw[2], lw[3]);
        return;
    }

    // ---------------- LayerNorm branch ----------------
    int row = bid;

    if (row < TT_ && tid < 64) {
        int d = tid;
        float ang = (float)row * invf.v[d];
        float sv, cv;
        sincosf(ang, &sv, &cv);
        g_cos[row * 64 + d] = cv;
        g_sin[row * 64 + d] = sv;
    }

    const float4* xr = (const float4*)(x + (size_t)row * DD_);
    float4 v[4];
    float s = 0.f, s2 = 0.f;
#pragma unroll
    for (int i = 0; i < 4; i++) {
        v[i] = xr[tid + i * 256];
        s  += v[i].x + v[i].y + v[i].z + v[i].w;
        s2 += v[i].x * v[i].x + v[i].y * v[i].y + v[i].z * v[i].z + v[i].w * v[i].w;
    }
    float* sh0 = &tile[0][0];
    float* sh1 = &tile[1][0];
    int lane = tid & 31, warp = tid >> 5;
#pragma unroll
    for (int off = 16; off > 0; off >>= 1) {
        s  += __shfl_down_sync(0xffffffffu, s,  off);
        s2 += __shfl_down_sync(0xffffffffu, s2, off);
    }
    if (lane == 0) { sh0[warp] = s; sh1[warp] = s2; }
    __syncthreads();
    if (warp == 0) {
        float a  = (lane < 8) ? sh0[lane] : 0.f;
        float b2 = (lane < 8) ? sh1[lane] : 0.f;
#pragma unroll
        for (int off = 4; off > 0; off >>= 1) {
            a  += __shfl_down_sync(0xffffffffu, a,  off);
            b2 += __shfl_down_sync(0xffffffffu, b2, off);
        }
        if (lane == 0) { sh0[0] = a; sh1[0] = b2; }
    }
    __syncthreads();
    float mu  = sh0[0] * (1.f / DD_);
    float var = sh1[0] * (1.f / DD_) - mu * mu;
    float rs  = rsqrtf(var + 1e-5f);

    const float4* g4 = (const float4*)gamma;
    const float4* b4 = (const float4*)beta;
    __nv_bfloat16* Ahi = g_A;
    __nv_bfloat16* Alo = g_A + (size_t)MM_ * DD_;
    size_t ro = (size_t)row * DD_;
#pragma unroll
    for (int i = 0; i < 4; i++) {
        int idx = tid + i * 256;
        float4 g = g4[idx], bt = b4[idx];
        float f[4];
        f[0] = (v[i].x - mu) * rs * g.x + bt.x;
        f[1] = (v[i].y - mu) * rs * g.y + bt.y;
        f[2] = (v[i].z - mu) * rs * g.z + bt.z;
        f[3] = (v[i].w - mu) * rs * g.w + bt.w;
        uint32_t uh[2], ul[2];
#pragma unroll
        for (int p = 0; p < 2; p++) {
            __nv_bfloat16 h0 = __float2bfloat16(f[2*p]);
            __nv_bfloat16 h1 = __float2bfloat16(f[2*p+1]);
            __nv_bfloat16 l0 = __float2bfloat16(f[2*p]   - __bfloat162float(h0));
            __nv_bfloat16 l1 = __float2bfloat16(f[2*p+1] - __bfloat162float(h1));
            uh[p] = (uint32_t)__bfloat16_as_ushort(h0) | ((uint32_t)__bfloat16_as_ushort(h1) << 16);
            ul[p] = (uint32_t)__bfloat16_as_ushort(l0) | ((uint32_t)__bfloat16_as_ushort(l1) << 16);
        }
        *(uint2*)(Ahi + ro + (size_t)idx * 4) = make_uint2(uh[0], uh[1]);
        *(uint2*)(Alo + ro + (size_t)idx * 4) = make_uint2(ul[0], ul[1]);
    }
}

// ---------------------------------------------------------------------------
// Kernel 2: PERSISTENT mma.sync bf16 GEMM.  148 CTAs, each processes tiles
//           bid, bid+148, ... of the 48x64 tile grid.  Stage/phase counters
//           carry across tiles so the TMA ring never drains: the producer
//           prefetches tile i+1 while consumers run tile i's epilogue.
//           CTA tile 128x128, warp tile 32x64, BK=128, 3 stages x 64KB,
//           early empty-arrive, fused RoPE + GQA scatter.  K' = 3*4096.
// ---------------------------------------------------------------------------
#define STAGES      3
#define BK          128
#define TM          128
#define TN          128
#define NTILE_X     (NTOT_ / TN)       // 48
#define NTILES      (NTILE_X * (MM_ / TM))  // 3072
#define NCTAS       148
#define KCHUNKS     32                 // 4096 / 128
#define KITERS      (3 * KCHUNKS)      // 96
#define SLAB        16384              // 128 rows x 64 k x 2B
#define STAGE_BYTES (4 * SLAB)         // 65536: [A0, A1, B0, B1]
#define SM_FULL(s)  ((s) * 16)
#define SM_EMPTY(s) ((s) * 16 + 8)
#define SM_DATA     1024
#define SMEM_TOTAL  (SM_DATA + STAGES * STAGE_BYTES)   // 197632

__global__ void __launch_bounds__(288, 1) gemm_rope_kernel(
    const __grid_constant__ CUtensorMap tmaA,
    const __grid_constant__ CUtensorMap tmaB,
    float* __restrict__ out)
{
    extern __shared__ char smem[];
    uint32_t sb = smem_u32(smem);
    const int tid = threadIdx.x, lane = tid & 31, wid = tid >> 5;
    const int bid = blockIdx.x;

    if (tid == 0) {
#pragma unroll
        for (int s = 0; s < STAGES; s++) {
            MBAR_INIT(sb + SM_FULL(s), 1);
            MBAR_INIT(sb + SM_EMPTY(s), 8);
        }
        asm volatile("fence.proxy.async.shared::cta;" ::: "memory");
    }
    __syncthreads();

    if (wid == 8) {
        // ---- producer warp: streams all tiles back-to-back ----
        if (lane == 0) {
            int s = 0, ph = 1;
            for (int tile = bid; tile < NTILES; tile += NCTAS) {
                int n0 = (tile % NTILE_X) * TN;
                int m0 = (tile / NTILE_X) * TM;
                for (int it = 0; it < KITERS; it++) {
                    MBAR_WAIT(sb + SM_EMPTY(s), ph);
                    MBAR_EXPECT_TX(sb + SM_FULL(s), STAGE_BYTES);
                    int p  = it >> 5;          // pass 0..2
                    int kc = it & 31;
                    int aseg = (p == 1) ? 1 : 0;
                    int bseg = (p == 2) ? 1 : 0;
                    uint32_t da = sb + SM_DATA + s * STAGE_BYTES;
                    int kx = kc * BK;
                    TMA_LOAD_3D(da,            &tmaA, kx,      m0, aseg, sb + SM_FULL(s));
                    TMA_LOAD_3D(da + SLAB,     &tmaA, kx + 64, m0, aseg, sb + SM_FULL(s));
                    TMA_LOAD_3D(da + 2*SLAB,   &tmaB, kx,      n0, bseg, sb + SM_FULL(s));
                    TMA_LOAD_3D(da + 3*SLAB,   &tmaB, kx + 64, n0, bseg, sb + SM_FULL(s));
                    if (++s == STAGES) { s = 0; ph ^= 1; }
                }
            }
        }
        return;
    }

    // ---- compute warps 0..7: warp tile 32(M) x 64(N)
    const int g      = wid & 1;
    const int warp_m = (wid >> 1) * 32;

    // lane-constant ldmatrix addressing (SW128 swizzle: kbyte ^ ((row&7)*16))
    uint32_t a_rowb[2], a_xor[2];
#pragma unroll
    for (int mt = 0; mt < 2; mt++) {
        int row = warp_m + mt * 16 + (lane & 15);
        a_rowb[mt] = row * 128;
        a_xor[mt]  = (row & 7) * 16;
    }
    const uint32_t a_kh = (lane >> 4) * 16;

    uint32_t b_rowb[4], b_xor[4];
#pragma unroll
    for (int p = 0; p < 4; p++) {
        int btile = g * 4 + p + (lane >> 4) * 8;
        int row   = btile * 8 + (lane & 7);
        b_rowb[p] = row * 128;
        b_xor[p]  = (row & 7) * 16;
    }
    const uint32_t b_kh = ((lane >> 3) & 1) * 16;

    const long long QSZ = (long long)BB_ * HH_ * TT_ * 128;
    const int qrow  = lane >> 2;
    const int qcol2 = (lane & 3) * 2;

    int s = 0, ph = 0;
    for (int tile = bid; tile < NTILES; tile += NCTAS) {
        const int n0 = (tile % NTILE_X) * TN;
        const int m0 = (tile / NTILE_X) * TM;

        float acc[2][4][2][4];
#pragma unroll
        for (int a1 = 0; a1 < 2; a1++)
#pragma unroll
            for (int a2 = 0; a2 < 4; a2++)
#pragma unroll
                for (int a3 = 0; a3 < 2; a3++)
#pragma unroll
                    for (int a4 = 0; a4 < 4; a4++) acc[a1][a2][a3][a4] = 0.f;

        for (int it = 0; it < KITERS; it++) {
            MBAR_WAIT(sb + SM_FULL(s), ph);
            uint32_t base = sb + SM_DATA + s * STAGE_BYTES;
#pragma unroll
            for (int ks = 0; ks < 8; ks++) {
                uint32_t slab  = (ks >= 4) ? SLAB : 0u;
                uint32_t kb    = (ks & 3) * 32;
                uint32_t baseA = base + slab;
                uint32_t baseB = base + 2 * SLAB + slab;
                uint32_t afr[2][4], bfr[4][4];
#pragma unroll
                for (int mt = 0; mt < 2; mt++)
                    LDSM4(afr[mt], baseA + a_rowb[mt] + ((kb + a_kh) ^ a_xor[mt]));
#pragma unroll
                for (int p = 0; p < 4; p++)
                    LDSM4(bfr[p], baseB + b_rowb[p] + ((kb + b_kh) ^ b_xor[p]));
                // early empty-arrive after the final LDSM batch of the stage
                if (ks == 7 && lane == 0) MBAR_ARRIVE(sb + SM_EMPTY(s));
#pragma unroll
                for (int mt = 0; mt < 2; mt++)
#pragma unroll
                    for (int p = 0; p < 4; p++) {
                        MMA16816(acc[mt][p][0], afr[mt], bfr[p][0], bfr[p][1]);
                        MMA16816(acc[mt][p][1], afr[mt], bfr[p][2], bfr[p][3]);
                    }
            }
            if (++s == STAGES) { s = 0; ph ^= 1; }
        }

        // ---- epilogue: RoPE + GQA scatter (producer keeps prefetching)
        const int region = (n0 < NQ_) ? 0 : ((n0 < NQ_ + NKV_) ? 1 : 2);

#pragma unroll
        for (int mt = 0; mt < 2; mt++)
#pragma unroll
            for (int rh = 0; rh < 2; rh++) {
                int m  = m0 + warp_m + mt * 16 + qrow + rh * 8;
                int b  = m >> 12, tp = m & (TT_ - 1);
#pragma unroll
                for (int p = 0; p < 4; p++) {
                    int   c0  = (g * 4 + p) * 8 + qcol2;   // d in [0,64)
                    float lo0 = acc[mt][p][0][rh * 2 + 0];
                    float lo1 = acc[mt][p][0][rh * 2 + 1];
                    float hi0 = acc[mt][p][1][rh * 2 + 0];
                    float hi1 = acc[mt][p][1][rh * 2 + 1];

                    if (region == 0) {
                        float2 cs = *(const float2*)&g_cos[tp * 64 + c0];
                        float2 sn = *(const float2*)&g_sin[tp * 64 + c0];
                        long long base = (((long long)(b * HH_ + (n0 >> 7))) * TT_ + tp) * 128;
                        *(float2*)&out[base + c0]      = make_float2(lo0 * cs.x - hi0 * sn.x,
                                                                     lo1 * cs.y - hi1 * sn.y);
                        *(float2*)&out[base + 64 + c0] = make_float2(hi0 * cs.x + lo0 * sn.x,
                                                                     hi1 * cs.y + lo1 * sn.y);
                    } else if (region == 1) {
                        float2 cs = *(const float2*)&g_cos[tp * 64 + c0];
                        float2 sn = *(const float2*)&g_sin[tp * 64 + c0];
                        float2 o0 = make_float2(lo0 * cs.x - hi0 * sn.x,
                                                lo1 * cs.y - hi1 * sn.y);
                        float2 o1 = make_float2(hi0 * cs.x + lo0 * sn.x,
                                                hi1 * cs.y + lo1 * sn.y);
                        int kv = (n0 - NQ_) >> 7;
#pragma unroll
                        for (int e = 0; e < 4; e++) {
                            long long base = QSZ +
                                (((long long)(b * HH_ + kv * 4 + e)) * TT_ + tp) * 128;
                            *(float2*)&out[base + c0]      = o0;
                            *(float2*)&out[base + 64 + c0] = o1;
                        }
                    } else {
                        int kv = (n0 - NQ_ - NKV_) >> 7;
                        float2 o0 = make_float2(lo0, lo1);
                        float2 o1 = make_float2(hi0, hi1);
#pragma unroll
                        for (int e = 0; e < 4; e++) {
                            long long base = 2 * QSZ +
                                (((long long)(b * HH_ + kv * 4 + e)) * TT_ + tp) * 128;
                            *(float2*)&out[base + c0]      = o0;
                            *(float2*)&out[base + 64 + c0] = o1;
                        }
                    }
                }
            }
    }
}

// ---------------------------------------------------------------------------
// Host launch
// ---------------------------------------------------------------------------
typedef CUresult (*PFN_encodeTiled)(
    CUtensorMap*, CUtensorMapDataType, cuuint32_t, void*,
    const cuuint64_t*, const cuuint64_t*, const cuuint32_t*, const cuuint32_t*,
    CUtensorMapInterleave, CUtensorMapSwizzle, CUtensorMapL2promotion,
    CUtensorMapFloatOOBfill);

extern "C" void kernel_launch(void* const* d_in, const int* in_sizes, int n_in,
                              void* d_out, int out_size)
{
    const float* x     = (const float*)d_in[0];
    const float* gamma = (const float*)d_in[1];
    const float* beta  = (const float*)d_in[2];
    const float* Wq    = (const float*)d_in[3];
    const float* Wk    = (const float*)d_in[4];
    const float* Wv    = (const float*)d_in[5];
    float* out = (float*)d_out;

    InvFreq invf;
    for (int d = 0; d < 64; d++)
        invf.v[d] = (float)exp(-((double)(2 * d) / 128.0) * log(10000.0));

    preamble_kernel<<<MM_ + WSPLIT_BLOCKS, 256>>>(x, gamma, beta, Wq, Wk, Wv, invf);

    PFN_encodeTiled encode = nullptr;
    cudaDriverEntryPointQueryResult qr;
    cudaGetDriverEntryPointByVersion("cuTensorMapEncodeTiled", (void**)&encode,
                                     12000, cudaEnableDefault, &qr);
    if (!encode) return;

    void *pa = nullptr, *pb = nullptr;
    cudaGetSymbolAddress(&pa, g_A);
    cudaGetSymbolAddress(&pb, g_Bm);

    CUtensorMap tmaA, tmaB;
    {
        cuuint64_t dims[3]    = {DD_, MM_, 2};
        cuuint64_t strides[2] = {(cuuint64_t)DD_ * 2, (cuuint64_t)MM_ * DD_ * 2};
        cuuint32_t box[3]     = {64, TM, 1};
        cuuint32_t es[3]      = {1, 1, 1};
        encode(&tmaA, CU_TENSOR_MAP_DATA_TYPE_BFLOAT16, 3, pa, dims, strides,
               box, es, CU_TENSOR_MAP_INTERLEAVE_NONE, CU_TENSOR_MAP_SWIZZLE_128B,
               CU_TENSOR_MAP_L2_PROMOTION_L2_128B, CU_TENSOR_MAP_FLOAT_OOB_FILL_NONE);
    }
    {
        cuuint64_t dims[3]    = {DD_, NTOT_, 2};
        cuuint64_t strides[2] = {(cuuint64_t)DD_ * 2, (cuuint64_t)NTOT_ * DD_ * 2};
        cuuint32_t box[3]     = {64, TN, 1};
        cuuint32_t es[3]      = {1, 1, 1};
        encode(&tmaB, CU_TENSOR_MAP_DATA_TYPE_BFLOAT16, 3, pb, dims, strides,
               box, es, CU_TENSOR_MAP_INTERLEAVE_NONE, CU_TENSOR_MAP_SWIZZLE_128B,
               CU_TENSOR_MAP_L2_PROMOTION_L2_128B, CU_TENSOR_MAP_FLOAT_OOB_FILL_NONE);
    }

    cudaFuncSetAttribute(gemm_rope_kernel,
                         cudaFuncAttributeMaxDynamicSharedMemorySize, SMEM_TOTAL);
    gemm_rope_kernel<<<NCTAS, 288, SMEM_TOTAL>>>(tmaA, tmaB, out);
}

// round 15
// speedup vs baseline: 1.0035x; 1.0035x over previous
#include <cuda_runtime.h>
#include <cuda.h>
#include <cuda_bf16.h>
#include <math.h>
#include <stdint.h>

// ---------------- problem constants ----------------
#define BB_   2
#define TT_   4096
#define DD_   4096
#define HH_   32
#define MM_   (BB_*TT_)          // 8192
#define NQ_   4096
#define NKV_  1024
#define NTOT_ 6144

// ---------------- scratch (device globals; no allocations allowed) --------
__device__ __nv_bfloat16 g_A[(size_t)2 * MM_ * DD_];    // [hi|lo][M][K]
__device__ __nv_bfloat16 g_Bm[(size_t)2 * NTOT_ * DD_]; // [hi|lo][N][K]
__device__ float g_cos[TT_ * 64];
__device__ float g_sin[TT_ * 64];

struct InvFreq { float v[64]; };

// ---------------- PTX helpers (all non-'a'-gated: sm_80/sm_90 ISA) --------
__device__ __forceinline__ uint32_t smem_u32(const void* p) {
    uint32_t a;
    asm("{ .reg .u64 t; cvta.to.shared.u64 t, %1; cvt.u32.u64 %0, t; }"
        : "=r"(a) : "l"(p));
    return a;
}

#define MBAR_INIT(a, c) \
    asm volatile("mbarrier.init.shared.b64 [%0], %1;" :: "r"(a), "r"(c) : "memory")

#define MBAR_ARRIVE(a) \
    asm volatile("mbarrier.arrive.shared.b64 _, [%0];" :: "r"(a) : "memory")

#define MBAR_EXPECT_TX(a, b) \
    asm volatile("mbarrier.arrive.expect_tx.shared.b64 _, [%0], %1;" :: "r"(a), "r"(b) : "memory")

#define MBAR_WAIT(addr, ph) do {                                              \
    uint32_t _m = (addr), _p = (ph), _d;                                      \
    asm volatile("{\n .reg .pred p;\n"                                        \
        " mbarrier.try_wait.parity.acquire.cta.shared::cta.b64 p, [%1], %2;\n"\
        " selp.b32 %0, 1, 0, p;\n}"                                           \
        : "=r"(_d) : "r"(_m), "r"(_p) : "memory");                            \
    if (!_d) {                                                                \
        asm volatile("{\n .reg .pred P1;\n"                                   \
            "WL%=:\n"                                                         \
            " mbarrier.try_wait.parity.acquire.cta.shared::cta.b64 P1, [%0], %1, 0x989680;\n" \
            " @P1 bra.uni WD%=;\n bra.uni WL%=;\nWD%=:\n}"                    \
            :: "r"(_m), "r"(_p) : "memory");                                  \
    } } while (0)

#define TMA_LOAD_3D(smem_addr, tmap, cx, cy, cz, mbar)                        \
    asm volatile(                                                             \
        "cp.async.bulk.tensor.3d.shared::cta.global.tile.mbarrier::complete_tx::bytes " \
        "[%0], [%1, {%2, %3, %4}], [%5];"                                     \
        :: "r"((uint32_t)(smem_addr)), "l"(tmap), "r"((int32_t)(cx)),         \
           "r"((int32_t)(cy)), "r"((int32_t)(cz)), "r"((uint32_t)(mbar))      \
        : "memory")

#define LDSM4(r, addr) \
    asm volatile("ldmatrix.sync.aligned.m8n8.x4.shared.b16 {%0,%1,%2,%3}, [%4];" \
        : "=r"((r)[0]), "=r"((r)[1]), "=r"((r)[2]), "=r"((r)[3]) : "r"(addr))

#define MMA16816(c, a, b0, b1) \
    asm volatile("mma.sync.aligned.m16n8k16.row.col.f32.bf16.bf16.f32 " \
        "{%0,%1,%2,%3}, {%4,%5,%6,%7}, {%8,%9}, {%0,%1,%2,%3};" \
        : "+f"((c)[0]), "+f"((c)[1]), "+f"((c)[2]), "+f"((c)[3]) \
        : "r"((a)[0]), "r"((a)[1]), "r"((a)[2]), "r"((a)[3]), "r"(b0), "r"(b1))

// ---------------------------------------------------------------------------
// Kernel 1: LayerNorm + bf16 hi/lo split of A + fused RoPE table
//           (inv_freq precomputed on host in double; fp32 trig on device)
// ---------------------------------------------------------------------------
__global__ __launch_bounds__(256) void ln_split_kernel(
    const float* __restrict__ x,
    const float* __restrict__ gamma,
    const float* __restrict__ beta,
    const __grid_constant__ InvFreq invf)
{
    int row = blockIdx.x;

    // fused RoPE table: blocks 0..4095, threads 0..63 compute t=row's entries.
    if (row < TT_ && threadIdx.x < 64) {
        int d = threadIdx.x;
        float ang = (float)row * invf.v[d];
        float sv, cv;
        sincosf(ang, &sv, &cv);
        g_cos[row * 64 + d] = cv;
        g_sin[row * 64 + d] = sv;
    }

    const float4* xr = (const float4*)(x + (size_t)row * DD_);
    float4 v[4];
    float s = 0.f, s2 = 0.f;
#pragma unroll
    for (int i = 0; i < 4; i++) {
        v[i] = xr[threadIdx.x + i * 256];
        s  += v[i].x + v[i].y + v[i].z + v[i].w;
        s2 += v[i].x * v[i].x + v[i].y * v[i].y + v[i].z * v[i].z + v[i].w * v[i].w;
    }
    __shared__ float sh[2][8];
    int lane = threadIdx.x & 31, warp = threadIdx.x >> 5;
#pragma unroll
    for (int off = 16; off > 0; off >>= 1) {
        s  += __shfl_down_sync(0xffffffffu, s,  off);
        s2 += __shfl_down_sync(0xffffffffu, s2, off);
    }
    if (lane == 0) { sh[0][warp] = s; sh[1][warp] = s2; }
    __syncthreads();
    if (warp == 0) {
        float a  = (lane < 8) ? sh[0][lane] : 0.f;
        float b2 = (lane < 8) ? sh[1][lane] : 0.f;
#pragma unroll
        for (int off = 4; off > 0; off >>= 1) {
            a  += __shfl_down_sync(0xffffffffu, a,  off);
            b2 += __shfl_down_sync(0xffffffffu, b2, off);
        }
        if (lane == 0) { sh[0][0] = a; sh[1][0] = b2; }
    }
    __syncthreads();
    float mu  = sh[0][0] * (1.f / DD_);
    float var = sh[1][0] * (1.f / DD_) - mu * mu;
    float rs  = rsqrtf(var + 1e-5f);

    const float4* g4 = (const float4*)gamma;
    const float4* b4 = (const float4*)beta;
    __nv_bfloat16* Ahi = g_A;
    __nv_bfloat16* Alo = g_A + (size_t)MM_ * DD_;
    size_t ro = (size_t)row * DD_;
#pragma unroll
    for (int i = 0; i < 4; i++) {
        int idx = threadIdx.x + i * 256;
        float4 g = g4[idx], bt = b4[idx];
        float f[4];
        f[0] = (v[i].x - mu) * rs * g.x + bt.x;
        f[1] = (v[i].y - mu) * rs * g.y + bt.y;
        f[2] = (v[i].z - mu) * rs * g.z + bt.z;
        f[3] = (v[i].w - mu) * rs * g.w + bt.w;
        uint32_t uh[2], ul[2];
#pragma unroll
        for (int p = 0; p < 2; p++) {
            __nv_bfloat16 h0 = __float2bfloat16(f[2*p]);
            __nv_bfloat16 h1 = __float2bfloat16(f[2*p+1]);
            __nv_bfloat16 l0 = __float2bfloat16(f[2*p]   - __bfloat162float(h0));
            __nv_bfloat16 l1 = __float2bfloat16(f[2*p+1] - __bfloat162float(h1));
            uh[p] = (uint32_t)__bfloat16_as_ushort(h0) | ((uint32_t)__bfloat16_as_ushort(h1) << 16);
            ul[p] = (uint32_t)__bfloat16_as_ushort(l0) | ((uint32_t)__bfloat16_as_ushort(l1) << 16);
        }
        *(uint2*)(Ahi + ro + (size_t)idx * 4) = make_uint2(uh[0], uh[1]);
        *(uint2*)(Alo + ro + (size_t)idx * 4) = make_uint2(ul[0], ul[1]);
    }
}

// ---------------------------------------------------------------------------
// Kernel 2: weight transpose + bf16 hi/lo split (vectorized).
//           Wq|Wk|Wv [K,N] -> g_Bm [N,K].  Tile 64k x 32n per block.
// ---------------------------------------------------------------------------
__global__ __launch_bounds__(256) void wsplit_kernel(
    const float* __restrict__ Wq,
    const float* __restrict__ Wk,
    const float* __restrict__ Wv)
{
    __shared__ float tile[64][33];
    int k0 = blockIdx.x * 64, n0 = blockIdx.y * 32;
    int tid = threadIdx.x;

    const float* W; int ld, nb;
    if (n0 < NQ_)            { W = Wq; ld = NQ_;  nb = n0; }
    else if (n0 < NQ_ + NKV_){ W = Wk; ld = NKV_; nb = n0 - NQ_; }
    else                     { W = Wv; ld = NKV_; nb = n0 - NQ_ - NKV_; }

#pragma unroll
    for (int i = 0; i < 8; i++) {
        int e = tid + i * 256;          // 0..2047
        int r = e >> 5, c = e & 31;
        tile[r][c] = W[(size_t)(k0 + r) * ld + nb + c];
    }
    __syncthreads();

    __nv_bfloat16* Bhi = g_Bm;
    __nv_bfloat16* Blo = g_Bm + (size_t)NTOT_ * DD_;
    int nl = tid >> 3;                 // 0..31
    int kg = (tid & 7) * 8;            // 0,8,..,56
    uint32_t hw[4], lw[4];
#pragma unroll
    for (int p = 0; p < 4; p++) {
        float f0 = tile[kg + 2*p + 0][nl];
        float f1 = tile[kg + 2*p + 1][nl];
        __nv_bfloat16 h0 = __float2bfloat16(f0);
        __nv_bfloat16 h1 = __float2bfloat16(f1);
        __nv_bfloat16 l0 = __float2bfloat16(f0 - __bfloat162float(h0));
        __nv_bfloat16 l1 = __float2bfloat16(f1 - __bfloat162float(h1));
        hw[p] = (uint32_t)__bfloat16_as_ushort(h0) | ((uint32_t)__bfloat16_as_ushort(h1) << 16);
        lw[p] = (uint32_t)__bfloat16_as_ushort(l0) | ((uint32_t)__bfloat16_as_ushort(l1) << 16);
    }
    size_t off = (size_t)(n0 + nl) * DD_ + k0 + kg;
    *(uint4*)(Bhi + off) = make_uint4(hw[0], hw[1], hw[2], hw[3]);
    *(uint4*)(Blo + off) = make_uint4(lw[0], lw[1], lw[2], lw[3]);
}

// ---------------------------------------------------------------------------
// Kernel 3: mma.sync bf16 GEMM, CTA tile 128x128, warp tile 32x64, BK=128
//           (two 64-k slabs per stage), 3-stage TMA pipeline, early
//           empty-arrive, fused RoPE + GQA scatter.  K' = 3*4096.
// ---------------------------------------------------------------------------
#define STAGES      3
#define BK          128
#define TM          128
#define TN          128
#define KCHUNKS     32                 // 4096 / 128
#define KITERS      (3 * KCHUNKS)      // 96
#define SLAB        16384              // 128 rows x 64 k x 2B
#define A_BYTES     (2 * SLAB)         // 32768
#define B_BYTES     (2 * SLAB)         // 32768
#define STAGE_BYTES (A_BYTES + B_BYTES)  // 65536
#define SM_FULL(s)  ((s) * 16)
#define SM_EMPTY(s) ((s) * 16 + 8)
#define SM_DATA     1024
#define SMEM_TOTAL  (SM_DATA + STAGES * STAGE_BYTES)   // 197632

__global__ void __launch_bounds__(288, 1) gemm_rope_kernel(
    const __grid_constant__ CUtensorMap tmaA,
    const __grid_constant__ CUtensorMap tmaB,
    float* __restrict__ out)
{
    extern __shared__ char smem[];
    uint32_t sb = smem_u32(smem);
    const int tid = threadIdx.x, lane = tid & 31, wid = tid >> 5;
    const int n0 = blockIdx.x * TN;
    const int m0 = blockIdx.y * TM;

    if (tid == 0) {
#pragma unroll
        for (int s = 0; s < STAGES; s++) {
            MBAR_INIT(sb + SM_FULL(s), 1);
            MBAR_INIT(sb + SM_EMPTY(s), 8);
        }
        asm volatile("fence.proxy.async.shared::cta;" ::: "memory");
    }
    __syncthreads();

    if (wid == 8) {
        // ---- producer warp ----
        if (lane == 0) {
            int s = 0, ph = 1;
            for (int it = 0; it < KITERS; it++) {
                MBAR_WAIT(sb + SM_EMPTY(s), ph);
                MBAR_EXPECT_TX(sb + SM_FULL(s), STAGE_BYTES);
                int p  = it >> 5;          // pass 0..2
                int kc = it & 31;
                int aseg = (p == 1) ? 1 : 0;
                int bseg = (p == 2) ? 1 : 0;
                uint32_t da = sb + SM_DATA + s * STAGE_BYTES;
                int kx = kc * BK;
                TMA_LOAD_3D(da,            &tmaA, kx,      m0, aseg, sb + SM_FULL(s));
                TMA_LOAD_3D(da + SLAB,     &tmaA, kx + 64, m0, aseg, sb + SM_FULL(s));
                TMA_LOAD_3D(da + 2*SLAB,   &tmaB, kx,      n0, bseg, sb + SM_FULL(s));
                TMA_LOAD_3D(da + 3*SLAB,   &tmaB, kx + 64, n0, bseg, sb + SM_FULL(s));
                if (++s == STAGES) { s = 0; ph ^= 1; }
            }
        }
        return;
    }

    // ---- compute warps 0..7: warp tile 32(M) x 64(N)
    const int g      = wid & 1;
    const int warp_m = (wid >> 1) * 32;

    float acc[2][4][2][4];
#pragma unroll
    for (int a1 = 0; a1 < 2; a1++)
#pragma unroll
        for (int a2 = 0; a2 < 4; a2++)
#pragma unroll
            for (int a3 = 0; a3 < 2; a3++)
#pragma unroll
                for (int a4 = 0; a4 < 4; a4++) acc[a1][a2][a3][a4] = 0.f;

    // lane-constant ldmatrix addressing (SW128 swizzle: kbyte ^ ((row&7)*16))
    uint32_t a_rowb[2], a_xor[2];
#pragma unroll
    for (int mt = 0; mt < 2; mt++) {
        int row = warp_m + mt * 16 + (lane & 15);
        a_rowb[mt] = row * 128;
        a_xor[mt]  = (row & 7) * 16;
    }
    const uint32_t a_kh = (lane >> 4) * 16;

    uint32_t b_rowb[4], b_xor[4];
#pragma unroll
    for (int p = 0; p < 4; p++) {
        int btile = g * 4 + p + (lane >> 4) * 8;
        int row   = btile * 8 + (lane & 7);
        b_rowb[p] = row * 128;
        b_xor[p]  = (row & 7) * 16;
    }
    const uint32_t b_kh = ((lane >> 3) & 1) * 16;

    {
        int s = 0, ph = 0;
        for (int it = 0; it < KITERS; it++) {
            MBAR_WAIT(sb + SM_FULL(s), ph);
            uint32_t base = sb + SM_DATA + s * STAGE_BYTES;
#pragma unroll
            for (int ks = 0; ks < 8; ks++) {
                uint32_t slab  = (ks >= 4) ? SLAB : 0u;
                uint32_t kb    = (ks & 3) * 32;
                uint32_t baseA = base + slab;
                uint32_t baseB = base + 2 * SLAB + slab;
                uint32_t afr[2][4], bfr[4][4];
#pragma unroll
                for (int mt = 0; mt < 2; mt++)
                    LDSM4(afr[mt], baseA + a_rowb[mt] + ((kb + a_kh) ^ a_xor[mt]));
#pragma unroll
                for (int p = 0; p < 4; p++)
                    LDSM4(bfr[p], baseB + b_rowb[p] + ((kb + b_kh) ^ b_xor[p]));
                // early empty-arrive after the final LDSM batch of the stage
                if (ks == 7 && lane == 0) MBAR_ARRIVE(sb + SM_EMPTY(s));
#pragma unroll
                for (int mt = 0; mt < 2; mt++)
#pragma unroll
                    for (int p = 0; p < 4; p++) {
                        MMA16816(acc[mt][p][0], afr[mt], bfr[p][0], bfr[p][1]);
                        MMA16816(acc[mt][p][1], afr[mt], bfr[p][2], bfr[p][3]);
                    }
            }
            if (++s == STAGES) { s = 0; ph ^= 1; }
        }
    }

    // ---- epilogue: RoPE + GQA scatter
    const long long QSZ = (long long)BB_ * HH_ * TT_ * 128;
    const int qrow  = lane >> 2;
    const int qcol2 = (lane & 3) * 2;
    const int region = (n0 < NQ_) ? 0 : ((n0 < NQ_ + NKV_) ? 1 : 2);

#pragma unroll
    for (int mt = 0; mt < 2; mt++)
#pragma unroll
        for (int rh = 0; rh < 2; rh++) {
            int m  = m0 + warp_m + mt * 16 + qrow + rh * 8;
            int b  = m >> 12, tp = m & (TT_ - 1);
#pragma unroll
            for (int p = 0; p < 4; p++) {
                int   c0  = (g * 4 + p) * 8 + qcol2;   // d in [0,64)
                float lo0 = acc[mt][p][0][rh * 2 + 0];
                float lo1 = acc[mt][p][0][rh * 2 + 1];
                float hi0 = acc[mt][p][1][rh * 2 + 0];
                float hi1 = acc[mt][p][1][rh * 2 + 1];

                if (region == 0) {
                    float2 cs = *(const float2*)&g_cos[tp * 64 + c0];
                    float2 sn = *(const float2*)&g_sin[tp * 64 + c0];
                    long long base = (((long long)(b * HH_ + (n0 >> 7))) * TT_ + tp) * 128;
                    *(float2*)&out[base + c0]      = make_float2(lo0 * cs.x - hi0 * sn.x,
                                                                 lo1 * cs.y - hi1 * sn.y);
                    *(float2*)&out[base + 64 + c0] = make_float2(hi0 * cs.x + lo0 * sn.x,
                                                                 hi1 * cs.y + lo1 * sn.y);
                } else if (region == 1) {
                    float2 cs = *(const float2*)&g_cos[tp * 64 + c0];
                    float2 sn = *(const float2*)&g_sin[tp * 64 + c0];
                    float2 o0 = make_float2(lo0 * cs.x - hi0 * sn.x,
                                            lo1 * cs.y - hi1 * sn.y);
                    float2 o1 = make_float2(hi0 * cs.x + lo0 * sn.x,
                                            hi1 * cs.y + lo1 * sn.y);
                    int kv = (n0 - NQ_) >> 7;
#pragma unroll
                    for (int e = 0; e < 4; e++) {
                        long long base = QSZ +
                            (((long long)(b * HH_ + kv * 4 + e)) * TT_ + tp) * 128;
                        *(float2*)&out[base + c0]      = o0;
                        *(float2*)&out[base + 64 + c0] = o1;
                    }
                } else {
                    int kv = (n0 - NQ_ - NKV_) >> 7;
                    float2 o0 = make_float2(lo0, lo1);
                    float2 o1 = make_float2(hi0, hi1);
#pragma unroll
                    for (int e = 0; e < 4; e++) {
                        long long base = 2 * QSZ +
                            (((long long)(b * HH_ + kv * 4 + e)) * TT_ + tp) * 128;
                        *(float2*)&out[base + c0]      = o0;
                        *(float2*)&out[base + 64 + c0] = o1;
                    }
                }
            }
        }
}

// ---------------------------------------------------------------------------
// Host launch
// ---------------------------------------------------------------------------
typedef CUresult (*PFN_encodeTiled)(
    CUtensorMap*, CUtensorMapDataType, cuuint32_t, void*,
    const cuuint64_t*, const cuuint64_t*, const cuuint32_t*, const cuuint32_t*,
    CUtensorMapInterleave, CUtensorMapSwizzle, CUtensorMapL2promotion,
    CUtensorMapFloatOOBfill);

extern "C" void kernel_launch(void* const* d_in, const int* in_sizes, int n_in,
                              void* d_out, int out_size)
{
    const float* x     = (const float*)d_in[0];
    const float* gamma = (const float*)d_in[1];
    const float* beta  = (const float*)d_in[2];
    const float* Wq    = (const float*)d_in[3];
    const float* Wk    = (const float*)d_in[4];
    const float* Wv    = (const float*)d_in[5];
    float* out = (float*)d_out;

    // host-computed inv_freq (double precision, rounded to fp32) — passed
    // by value so the graph bakes it into the launch node.
    InvFreq invf;
    for (int d = 0; d < 64; d++)
        invf.v[d] = (float)exp(-((double)(2 * d) / 128.0) * log(10000.0));

    ln_split_kernel<<<MM_, 256>>>(x, gamma, beta, invf);
    wsplit_kernel<<<dim3(DD_ / 64, NTOT_ / 32), 256>>>(Wq, Wk, Wv);

    PFN_encodeTiled encode = nullptr;
    cudaDriverEntryPointQueryResult qr;
    cudaGetDriverEntryPointByVersion("cuTensorMapEncodeTiled", (void**)&encode,
                                     12000, cudaEnableDefault, &qr);
    if (!encode) return;

    void *pa = nullptr, *pb = nullptr;
    cudaGetSymbolAddress(&pa, g_A);
    cudaGetSymbolAddress(&pb, g_Bm);

    CUtensorMap tmaA, tmaB;
    {
        cuuint64_t dims[3]    = {DD_, MM_, 2};
        cuuint64_t strides[2] = {(cuuint64_t)DD_ * 2, (cuuint64_t)MM_ * DD_ * 2};
        cuuint32_t box[3]     = {64, TM, 1};
        cuuint32_t es[3]      = {1, 1, 1};
        encode(&tmaA, CU_TENSOR_MAP_DATA_TYPE_BFLOAT16, 3, pa, dims, strides,
               box, es, CU_TENSOR_MAP_INTERLEAVE_NONE, CU_TENSOR_MAP_SWIZZLE_128B,
               CU_TENSOR_MAP_L2_PROMOTION_L2_128B, CU_TENSOR_MAP_FLOAT_OOB_FILL_NONE);
    }
    {
        cuuint64_t dims[3]    = {DD_, NTOT_, 2};
        cuuint64_t strides[2] = {(cuuint64_t)DD_ * 2, (cuuint64_t)NTOT_ * DD_ * 2};
        cuuint32_t box[3]     = {64, TN, 1};
        cuuint32_t es[3]      = {1, 1, 1};
        encode(&tmaB, CU_TENSOR_MAP_DATA_TYPE_BFLOAT16, 3, pb, dims, strides,
               box, es, CU_TENSOR_MAP_INTERLEAVE_NONE, CU_TENSOR_MAP_SWIZZLE_128B,
               CU_TENSOR_MAP_L2_PROMOTION_L2_128B, CU_TENSOR_MAP_FLOAT_OOB_FILL_NONE);
    }

    cudaFuncSetAttribute(gemm_rope_kernel,
                         cudaFuncAttributeMaxDynamicSharedMemorySize, SMEM_TOTAL);
    dim3 grid(NTOT_ / TN, MM_ / TM);   // 48 x 64
    gemm_rope_kernel<<<grid, 288, SMEM_TOTAL>>>(tmaA, tmaB, out);
}

// round 16
// speedup vs baseline: 1.0036x; 1.0002x over previous
#include <cuda_runtime.h>
#include <cuda.h>
#include <cuda_bf16.h>
#include <math.h>
#include <stdint.h>

// ---------------- problem constants ----------------
#define BB_   2
#define TT_   4096
#define DD_   4096
#define HH_   32
#define MM_   (BB_*TT_)          // 8192
#define NQ_   4096
#define NKV_  1024
#define NTOT_ 6144

// ---------------- scratch (device globals; no allocations allowed) --------
__device__ __nv_bfloat16 g_A[(size_t)2 * MM_ * DD_];    // [hi|lo][M][K]
__device__ __nv_bfloat16 g_Bm[(size_t)2 * NTOT_ * DD_]; // [hi|lo][N][K]
__device__ float g_cos[TT_ * 64];
__device__ float g_sin[TT_ * 64];

struct InvFreq { float v[64]; };

// ---------------- PTX helpers (all non-'a'-gated: sm_80/sm_90 ISA) --------
__device__ __forceinline__ uint32_t smem_u32(const void* p) {
    uint32_t a;
    asm("{ .reg .u64 t; cvta.to.shared.u64 t, %1; cvt.u32.u64 %0, t; }"
        : "=r"(a) : "l"(p));
    return a;
}

#define MBAR_INIT(a, c) \
    asm volatile("mbarrier.init.shared.b64 [%0], %1;" :: "r"(a), "r"(c) : "memory")

#define MBAR_ARRIVE(a) \
    asm volatile("mbarrier.arrive.shared.b64 _, [%0];" :: "r"(a) : "memory")

#define MBAR_EXPECT_TX(a, b) \
    asm volatile("mbarrier.arrive.expect_tx.shared.b64 _, [%0], %1;" :: "r"(a), "r"(b) : "memory")

#define MBAR_WAIT(addr, ph) do {                                              \
    uint32_t _m = (addr), _p = (ph), _d;                                      \
    asm volatile("{\n .reg .pred p;\n"                                        \
        " mbarrier.try_wait.parity.acquire.cta.shared::cta.b64 p, [%1], %2;\n"\
        " selp.b32 %0, 1, 0, p;\n}"                                           \
        : "=r"(_d) : "r"(_m), "r"(_p) : "memory");                            \
    if (!_d) {                                                                \
        asm volatile("{\n .reg .pred P1;\n"                                   \
            "WL%=:\n"                                                         \
            " mbarrier.try_wait.parity.acquire.cta.shared::cta.b64 P1, [%0], %1, 0x989680;\n" \
            " @P1 bra.uni WD%=;\n bra.uni WL%=;\nWD%=:\n}"                    \
            :: "r"(_m), "r"(_p) : "memory");                                  \
    } } while (0)

#define TMA_PREFETCH(tmap) \
    asm volatile("prefetch.tensormap [%0];" :: "l"(tmap))

#define TMA_LOAD_3D(smem_addr, tmap, cx, cy, cz, mbar)                        \
    asm volatile(                                                             \
        "cp.async.bulk.tensor.3d.shared::cta.global.tile.mbarrier::complete_tx::bytes " \
        "[%0], [%1, {%2, %3, %4}], [%5];"                                     \
        :: "r"((uint32_t)(smem_addr)), "l"(tmap), "r"((int32_t)(cx)),         \
           "r"((int32_t)(cy)), "r"((int32_t)(cz)), "r"((uint32_t)(mbar))      \
        : "memory")

#define LDSM4(r, addr) \
    asm volatile("ldmatrix.sync.aligned.m8n8.x4.shared.b16 {%0,%1,%2,%3}, [%4];" \
        : "=r"((r)[0]), "=r"((r)[1]), "=r"((r)[2]), "=r"((r)[3]) : "r"(addr))

#define MMA16816(c, a, b0, b1) \
    asm volatile("mma.sync.aligned.m16n8k16.row.col.f32.bf16.bf16.f32 " \
        "{%0,%1,%2,%3}, {%4,%5,%6,%7}, {%8,%9}, {%0,%1,%2,%3};" \
        : "+f"((c)[0]), "+f"((c)[1]), "+f"((c)[2]), "+f"((c)[3]) \
        : "r"((a)[0]), "r"((a)[1]), "r"((a)[2]), "r"((a)[3]), "r"(b0), "r"(b1))

// ---------------------------------------------------------------------------
// Kernel 1: LayerNorm + bf16 hi/lo split of A + fused RoPE table
//           (inv_freq precomputed on host in double; fp32 trig on device)
// ---------------------------------------------------------------------------
__global__ __launch_bounds__(256) void ln_split_kernel(
    const float* __restrict__ x,
    const float* __restrict__ gamma,
    const float* __restrict__ beta,
    const __grid_constant__ InvFreq invf)
{
    int row = blockIdx.x;

    // fused RoPE table: blocks 0..4095, threads 0..63 compute t=row's entries.
    if (row < TT_ && threadIdx.x < 64) {
        int d = threadIdx.x;
        float ang = (float)row * invf.v[d];
        float sv, cv;
        sincosf(ang, &sv, &cv);
        g_cos[row * 64 + d] = cv;
        g_sin[row * 64 + d] = sv;
    }

    const float4* xr = (const float4*)(x + (size_t)row * DD_);
    float4 v[4];
    float s = 0.f, s2 = 0.f;
#pragma unroll
    for (int i = 0; i < 4; i++) {
        v[i] = xr[threadIdx.x + i * 256];
        s  += v[i].x + v[i].y + v[i].z + v[i].w;
        s2 += v[i].x * v[i].x + v[i].y * v[i].y + v[i].z * v[i].z + v[i].w * v[i].w;
    }
    __shared__ float sh[2][8];
    int lane = threadIdx.x & 31, warp = threadIdx.x >> 5;
#pragma unroll
    for (int off = 16; off > 0; off >>= 1) {
        s  += __shfl_down_sync(0xffffffffu, s,  off);
        s2 += __shfl_down_sync(0xffffffffu, s2, off);
    }
    if (lane == 0) { sh[0][warp] = s; sh[1][warp] = s2; }
    __syncthreads();
    if (warp == 0) {
        float a  = (lane < 8) ? sh[0][lane] : 0.f;
        float b2 = (lane < 8) ? sh[1][lane] : 0.f;
#pragma unroll
        for (int off = 4; off > 0; off >>= 1) {
            a  += __shfl_down_sync(0xffffffffu, a,  off);
            b2 += __shfl_down_sync(0xffffffffu, b2, off);
        }
        if (lane == 0) { sh[0][0] = a; sh[1][0] = b2; }
    }
    __syncthreads();
    float mu  = sh[0][0] * (1.f / DD_);
    float var = sh[1][0] * (1.f / DD_) - mu * mu;
    float rs  = rsqrtf(var + 1e-5f);

    const float4* g4 = (const float4*)gamma;
    const float4* b4 = (const float4*)beta;
    __nv_bfloat16* Ahi = g_A;
    __nv_bfloat16* Alo = g_A + (size_t)MM_ * DD_;
    size_t ro = (size_t)row * DD_;
#pragma unroll
    for (int i = 0; i < 4; i++) {
        int idx = threadIdx.x + i * 256;
        float4 g = g4[idx], bt = b4[idx];
        float f[4];
        f[0] = (v[i].x - mu) * rs * g.x + bt.x;
        f[1] = (v[i].y - mu) * rs * g.y + bt.y;
        f[2] = (v[i].z - mu) * rs * g.z + bt.z;
        f[3] = (v[i].w - mu) * rs * g.w + bt.w;
        uint32_t uh[2], ul[2];
#pragma unroll
        for (int p = 0; p < 2; p++) {
            __nv_bfloat16 h0 = __float2bfloat16(f[2*p]);
            __nv_bfloat16 h1 = __float2bfloat16(f[2*p+1]);
            __nv_bfloat16 l0 = __float2bfloat16(f[2*p]   - __bfloat162float(h0));
            __nv_bfloat16 l1 = __float2bfloat16(f[2*p+1] - __bfloat162float(h1));
            uh[p] = (uint32_t)__bfloat16_as_ushort(h0) | ((uint32_t)__bfloat16_as_ushort(h1) << 16);
            ul[p] = (uint32_t)__bfloat16_as_ushort(l0) | ((uint32_t)__bfloat16_as_ushort(l1) << 16);
        }
        *(uint2*)(Ahi + ro + (size_t)idx * 4) = make_uint2(uh[0], uh[1]);
        *(uint2*)(Alo + ro + (size_t)idx * 4) = make_uint2(ul[0], ul[1]);
    }
}

// ---------------------------------------------------------------------------
// Kernel 2: weight transpose + bf16 hi/lo split (vectorized).
//           Wq|Wk|Wv [K,N] -> g_Bm [N,K].  Tile 64k x 32n per block.
// ---------------------------------------------------------------------------
__global__ __launch_bounds__(256) void wsplit_kernel(
    const float* __restrict__ Wq,
    const float* __restrict__ Wk,
    const float* __restrict__ Wv)
{
    __shared__ float tile[64][33];
    int k0 = blockIdx.x * 64, n0 = blockIdx.y * 32;
    int tid = threadIdx.x;

    const float* W; int ld, nb;
    if (n0 < NQ_)            { W = Wq; ld = NQ_;  nb = n0; }
    else if (n0 < NQ_ + NKV_){ W = Wk; ld = NKV_; nb = n0 - NQ_; }
    else                     { W = Wv; ld = NKV_; nb = n0 - NQ_ - NKV_; }

#pragma unroll
    for (int i = 0; i < 8; i++) {
        int e = tid + i * 256;          // 0..2047
        int r = e >> 5, c = e & 31;
        tile[r][c] = W[(size_t)(k0 + r) * ld + nb + c];
    }
    __syncthreads();

    __nv_bfloat16* Bhi = g_Bm;
    __nv_bfloat16* Blo = g_Bm + (size_t)NTOT_ * DD_;
    int nl = tid >> 3;                 // 0..31
    int kg = (tid & 7) * 8;            // 0,8,..,56
    uint32_t hw[4], lw[4];
#pragma unroll
    for (int p = 0; p < 4; p++) {
        float f0 = tile[kg + 2*p + 0][nl];
        float f1 = tile[kg + 2*p + 1][nl];
        __nv_bfloat16 h0 = __float2bfloat16(f0);
        __nv_bfloat16 h1 = __float2bfloat16(f1);
        __nv_bfloat16 l0 = __float2bfloat16(f0 - __bfloat162float(h0));
        __nv_bfloat16 l1 = __float2bfloat16(f1 - __bfloat162float(h1));
        hw[p] = (uint32_t)__bfloat16_as_ushort(h0) | ((uint32_t)__bfloat16_as_ushort(h1) << 16);
        lw[p] = (uint32_t)__bfloat16_as_ushort(l0) | ((uint32_t)__bfloat16_as_ushort(l1) << 16);
    }
    size_t off = (size_t)(n0 + nl) * DD_ + k0 + kg;
    *(uint4*)(Bhi + off) = make_uint4(hw[0], hw[1], hw[2], hw[3]);
    *(uint4*)(Blo + off) = make_uint4(lw[0], lw[1], lw[2], lw[3]);
}

// ---------------------------------------------------------------------------
// Kernel 3: mma.sync bf16 GEMM, CTA tile 128x128, warp tile 32x64, BK=128
//           (two 64-k slabs per stage), 3-stage TMA pipeline, tensormap
//           prefetch, early empty-arrive, fused RoPE + GQA scatter.
//           K' = 3*4096 (Ootomo 3-pass split).
// ---------------------------------------------------------------------------
#define STAGES      3
#define BK          128
#define TM          128
#define TN          128
#define KCHUNKS     32                 // 4096 / 128
#define KITERS      (3 * KCHUNKS)      // 96
#define SLAB        16384              // 128 rows x 64 k x 2B
#define A_BYTES     (2 * SLAB)         // 32768
#define B_BYTES     (2 * SLAB)         // 32768
#define STAGE_BYTES (A_BYTES + B_BYTES)  // 65536
#define SM_FULL(s)  ((s) * 16)
#define SM_EMPTY(s) ((s) * 16 + 8)
#define SM_DATA     1024
#define SMEM_TOTAL  (SM_DATA + STAGES * STAGE_BYTES)   // 197632

__global__ void __launch_bounds__(288, 1) gemm_rope_kernel(
    const __grid_constant__ CUtensorMap tmaA,
    const __grid_constant__ CUtensorMap tmaB,
    float* __restrict__ out)
{
    extern __shared__ char smem[];
    uint32_t sb = smem_u32(smem);
    const int tid = threadIdx.x, lane = tid & 31, wid = tid >> 5;
    const int n0 = blockIdx.x * TN;
    const int m0 = blockIdx.y * TM;

    // prefetch tensormap descriptors — overlaps with mbarrier init + sync
    if (wid == 8 && lane == 0) {
        TMA_PREFETCH(&tmaA);
        TMA_PREFETCH(&tmaB);
    }

    if (tid == 0) {
#pragma unroll
        for (int s = 0; s < STAGES; s++) {
            MBAR_INIT(sb + SM_FULL(s), 1);
            MBAR_INIT(sb + SM_EMPTY(s), 8);
        }
        asm volatile("fence.proxy.async.shared::cta;" ::: "memory");
    }
    __syncthreads();

    if (wid == 8) {
        // ---- producer warp ----
        if (lane == 0) {
            int s = 0, ph = 1;
            for (int it = 0; it < KITERS; it++) {
                MBAR_WAIT(sb + SM_EMPTY(s), ph);
                MBAR_EXPECT_TX(sb + SM_FULL(s), STAGE_BYTES);
                int p  = it >> 5;          // pass 0..2
                int kc = it & 31;
                int aseg = (p == 1) ? 1 : 0;
                int bseg = (p == 2) ? 1 : 0;
                uint32_t da = sb + SM_DATA + s * STAGE_BYTES;
                int kx = kc * BK;
                TMA_LOAD_3D(da,            &tmaA, kx,      m0, aseg, sb + SM_FULL(s));
                TMA_LOAD_3D(da + SLAB,     &tmaA, kx + 64, m0, aseg, sb + SM_FULL(s));
                TMA_LOAD_3D(da + 2*SLAB,   &tmaB, kx,      n0, bseg, sb + SM_FULL(s));
                TMA_LOAD_3D(da + 3*SLAB,   &tmaB, kx + 64, n0, bseg, sb + SM_FULL(s));
                if (++s == STAGES) { s = 0; ph ^= 1; }
            }
        }
        return;
    }

    // ---- compute warps 0..7: warp tile 32(M) x 64(N)
    const int g      = wid & 1;
    const int warp_m = (wid >> 1) * 32;

    float acc[2][4][2][4];
#pragma unroll
    for (int a1 = 0; a1 < 2; a1++)
#pragma unroll
        for (int a2 = 0; a2 < 4; a2++)
#pragma unroll
            for (int a3 = 0; a3 < 2; a3++)
#pragma unroll
                for (int a4 = 0; a4 < 4; a4++) acc[a1][a2][a3][a4] = 0.f;

    // lane-constant ldmatrix addressing (SW128 swizzle: kbyte ^ ((row&7)*16))
    uint32_t a_rowb[2], a_xor[2];
#pragma unroll
    for (int mt = 0; mt < 2; mt++) {
        int row = warp_m + mt * 16 + (lane & 15);
        a_rowb[mt] = row * 128;
        a_xor[mt]  = (row & 7) * 16;
    }
    const uint32_t a_kh = (lane >> 4) * 16;

    uint32_t b_rowb[4], b_xor[4];
#pragma unroll
    for (int p = 0; p < 4; p++) {
        int btile = g * 4 + p + (lane >> 4) * 8;
        int row   = btile * 8 + (lane & 7);
        b_rowb[p] = row * 128;
        b_xor[p]  = (row & 7) * 16;
    }
    const uint32_t b_kh = ((lane >> 3) & 1) * 16;

    {
        int s = 0, ph = 0;
        for (int it = 0; it < KITERS; it++) {
            MBAR_WAIT(sb + SM_FULL(s), ph);
            uint32_t base = sb + SM_DATA + s * STAGE_BYTES;
#pragma unroll
            for (int ks = 0; ks < 8; ks++) {
                uint32_t slab  = (ks >= 4) ? SLAB : 0u;
                uint32_t kb    = (ks & 3) * 32;
                uint32_t baseA = base + slab;
                uint32_t baseB = base + 2 * SLAB + slab;
                uint32_t afr[2][4], bfr[4][4];
#pragma unroll
                for (int mt = 0; mt < 2; mt++)
                    LDSM4(afr[mt], baseA + a_rowb[mt] + ((kb + a_kh) ^ a_xor[mt]));
#pragma unroll
                for (int p = 0; p < 4; p++)
                    LDSM4(bfr[p], baseB + b_rowb[p] + ((kb + b_kh) ^ b_xor[p]));
                // early empty-arrive after the final LDSM batch of the stage
                if (ks == 7 && lane == 0) MBAR_ARRIVE(sb + SM_EMPTY(s));
#pragma unroll
                for (int mt = 0; mt < 2; mt++)
#pragma unroll
                    for (int p = 0; p < 4; p++) {
                        MMA16816(acc[mt][p][0], afr[mt], bfr[p][0], bfr[p][1]);
                        MMA16816(acc[mt][p][1], afr[mt], bfr[p][2], bfr[p][3]);
                    }
            }
            if (++s == STAGES) { s = 0; ph ^= 1; }
        }
    }

    // ---- epilogue: RoPE + GQA scatter
    const long long QSZ = (long long)BB_ * HH_ * TT_ * 128;
    const int qrow  = lane >> 2;
    const int qcol2 = (lane & 3) * 2;
    const int region = (n0 < NQ_) ? 0 : ((n0 < NQ_ + NKV_) ? 1 : 2);

#pragma unroll
    for (int mt = 0; mt < 2; mt++)
#pragma unroll
        for (int rh = 0; rh < 2; rh++) {
            int m  = m0 + warp_m + mt * 16 + qrow + rh * 8;
            int b  = m >> 12, tp = m & (TT_ - 1);
#pragma unroll
            for (int p = 0; p < 4; p++) {
                int   c0  = (g * 4 + p) * 8 + qcol2;   // d in [0,64)
                float lo0 = acc[mt][p][0][rh * 2 + 0];
                float lo1 = acc[mt][p][0][rh * 2 + 1];
                float hi0 = acc[mt][p][1][rh * 2 + 0];
                float hi1 = acc[mt][p][1][rh * 2 + 1];

                if (region == 0) {
                    float2 cs = *(const float2*)&g_cos[tp * 64 + c0];
                    float2 sn = *(const float2*)&g_sin[tp * 64 + c0];
                    long long base = (((long long)(b * HH_ + (n0 >> 7))) * TT_ + tp) * 128;
                    *(float2*)&out[base + c0]      = make_float2(lo0 * cs.x - hi0 * sn.x,
                                                                 lo1 * cs.y - hi1 * sn.y);
                    *(float2*)&out[base + 64 + c0] = make_float2(hi0 * cs.x + lo0 * sn.x,
                                                                 hi1 * cs.y + lo1 * sn.y);
                } else if (region == 1) {
                    float2 cs = *(const float2*)&g_cos[tp * 64 + c0];
                    float2 sn = *(const float2*)&g_sin[tp * 64 + c0];
                    float2 o0 = make_float2(lo0 * cs.x - hi0 * sn.x,
                                            lo1 * cs.y - hi1 * sn.y);
                    float2 o1 = make_float2(hi0 * cs.x + lo0 * sn.x,
                                            hi1 * cs.y + lo1 * sn.y);
                    int kv = (n0 - NQ_) >> 7;
#pragma unroll
                    for (int e = 0; e < 4; e++) {
                        long long base = QSZ +
                            (((long long)(b * HH_ + kv * 4 + e)) * TT_ + tp) * 128;
                        *(float2*)&out[base + c0]      = o0;
                        *(float2*)&out[base + 64 + c0] = o1;
                    }
                } else {
                    int kv = (n0 - NQ_ - NKV_) >> 7;
                    float2 o0 = make_float2(lo0, lo1);
                    float2 o1 = make_float2(hi0, hi1);
#pragma unroll
                    for (int e = 0; e < 4; e++) {
                        long long base = 2 * QSZ +
                            (((long long)(b * HH_ + kv * 4 + e)) * TT_ + tp) * 128;
                        *(float2*)&out[base + c0]      = o0;
                        *(float2*)&out[base + 64 + c0] = o1;
                    }
                }
            }
        }
}

// ---------------------------------------------------------------------------
// Host launch
// ---------------------------------------------------------------------------
typedef CUresult (*PFN_encodeTiled)(
    CUtensorMap*, CUtensorMapDataType, cuuint32_t, void*,
    const cuuint64_t*, const cuuint64_t*, const cuuint32_t*, const cuuint32_t*,
    CUtensorMapInterleave, CUtensorMapSwizzle, CUtensorMapL2promotion,
    CUtensorMapFloatOOBfill);

extern "C" void kernel_launch(void* const* d_in, const int* in_sizes, int n_in,
                              void* d_out, int out_size)
{
    const float* x     = (const float*)d_in[0];
    const float* gamma = (const float*)d_in[1];
    const float* beta  = (const float*)d_in[2];
    const float* Wq    = (const float*)d_in[3];
    const float* Wk    = (const float*)d_in[4];
    const float* Wv    = (const float*)d_in[5];
    float* out = (float*)d_out;

    // host-computed inv_freq (double precision, rounded to fp32) — passed
    // by value so the graph bakes it into the launch node.
    InvFreq invf;
    for (int d = 0; d < 64; d++)
        invf.v[d] = (float)exp(-((double)(2 * d) / 128.0) * log(10000.0));

    ln_split_kernel<<<MM_, 256>>>(x, gamma, beta, invf);
    wsplit_kernel<<<dim3(DD_ / 64, NTOT_ / 32), 256>>>(Wq, Wk, Wv);

    PFN_encodeTiled encode = nullptr;
    cudaDriverEntryPointQueryResult qr;
    cudaGetDriverEntryPointByVersion("cuTensorMapEncodeTiled", (void**)&encode,
                                     12000, cudaEnableDefault, &qr);
    if (!encode) return;

    void *pa = nullptr, *pb = nullptr;
    cudaGetSymbolAddress(&pa, g_A);
    cudaGetSymbolAddress(&pb, g_Bm);

    CUtensorMap tmaA, tmaB;
    {
        cuuint64_t dims[3]    = {DD_, MM_, 2};
        cuuint64_t strides[2] = {(cuuint64_t)DD_ * 2, (cuuint64_t)MM_ * DD_ * 2};
        cuuint32_t box[3]     = {64, TM, 1};
        cuuint32_t es[3]      = {1, 1, 1};
        encode(&tmaA, CU_TENSOR_MAP_DATA_TYPE_BFLOAT16, 3, pa, dims, strides,
               box, es, CU_TENSOR_MAP_INTERLEAVE_NONE, CU_TENSOR_MAP_SWIZZLE_128B,
               CU_TENSOR_MAP_L2_PROMOTION_L2_128B, CU_TENSOR_MAP_FLOAT_OOB_FILL_NONE);
    }
    {
        cuuint64_t dims[3]    = {DD_, NTOT_, 2};
        cuuint64_t strides[2] = {(cuuint64_t)DD_ * 2, (cuuint64_t)NTOT_ * DD_ * 2};
        cuuint32_t box[3]     = {64, TN, 1};
        cuuint32_t es[3]      = {1, 1, 1};
        encode(&tmaB, CU_TENSOR_MAP_DATA_TYPE_BFLOAT16, 3, pb, dims, strides,
               box, es, CU_TENSOR_MAP_INTERLEAVE_NONE, CU_TENSOR_MAP_SWIZZLE_128B,
               CU_TENSOR_MAP_L2_PROMOTION_L2_128B, CU_TENSOR_MAP_FLOAT_OOB_FILL_NONE);
    }

    cudaFuncSetAttribute(gemm_rope_kernel,
                         cudaFuncAttributeMaxDynamicSharedMemorySize, SMEM_TOTAL);
    dim3 grid(NTOT_ / TN, MM_ / TM);   // 48 x 64
    gemm_rope_kernel<<<grid, 288, SMEM_TOTAL>>>(tmaA, tmaB, out);
}

// round 17
// speedup vs baseline: 1.0037x; 1.0001x over previous
#include <cuda_runtime.h>
#include <cuda.h>
#include <cuda_bf16.h>
#include <math.h>
#include <stdint.h>

// ---------------- problem constants ----------------
#define BB_   2
#define TT_   4096
#define DD_   4096
#define HH_   32
#define MM_   (BB_*TT_)          // 8192
#define NQ_   4096
#define NKV_  1024
#define NTOT_ 6144

// ---------------- scratch (device globals; no allocations allowed) --------
__device__ __nv_bfloat16 g_A[(size_t)2 * MM_ * DD_];    // [hi|lo][M][K]
__device__ __nv_bfloat16 g_Bm[(size_t)2 * NTOT_ * DD_]; // [hi|lo][N][K]
__device__ float g_cos[TT_ * 64];
__device__ float g_sin[TT_ * 64];

struct InvFreq { float v[64]; };

// ---------------- PTX helpers (all non-'a'-gated: sm_80/sm_90 ISA) --------
__device__ __forceinline__ uint32_t smem_u32(const void* p) {
    uint32_t a;
    asm("{ .reg .u64 t; cvta.to.shared.u64 t, %1; cvt.u32.u64 %0, t; }"
        : "=r"(a) : "l"(p));
    return a;
}

#define MBAR_INIT(a, c) \
    asm volatile("mbarrier.init.shared.b64 [%0], %1;" :: "r"(a), "r"(c) : "memory")

#define MBAR_ARRIVE(a) \
    asm volatile("mbarrier.arrive.shared.b64 _, [%0];" :: "r"(a) : "memory")

#define MBAR_EXPECT_TX(a, b) \
    asm volatile("mbarrier.arrive.expect_tx.shared.b64 _, [%0], %1;" :: "r"(a), "r"(b) : "memory")

#define MBAR_WAIT(addr, ph) do {                                              \
    uint32_t _m = (addr), _p = (ph), _d;                                      \
    asm volatile("{\n .reg .pred p;\n"                                        \
        " mbarrier.try_wait.parity.acquire.cta.shared::cta.b64 p, [%1], %2;\n"\
        " selp.b32 %0, 1, 0, p;\n}"                                           \
        : "=r"(_d) : "r"(_m), "r"(_p) : "memory");                            \
    if (!_d) {                                                                \
        asm volatile("{\n .reg .pred P1;\n"                                   \
            "WL%=:\n"                                                         \
            " mbarrier.try_wait.parity.acquire.cta.shared::cta.b64 P1, [%0], %1, 0x989680;\n" \
            " @P1 bra.uni WD%=;\n bra.uni WL%=;\nWD%=:\n}"                    \
            :: "r"(_m), "r"(_p) : "memory");                                  \
    } } while (0)

#define TMA_PREFETCH(tmap) \
    asm volatile("prefetch.tensormap [%0];" :: "l"(tmap))

#define TMA_LOAD_3D(smem_addr, tmap, cx, cy, cz, mbar)                        \
    asm volatile(                                                             \
        "cp.async.bulk.tensor.3d.shared::cta.global.tile.mbarrier::complete_tx::bytes " \
        "[%0], [%1, {%2, %3, %4}], [%5];"                                     \
        :: "r"((uint32_t)(smem_addr)), "l"(tmap), "r"((int32_t)(cx)),         \
           "r"((int32_t)(cy)), "r"((int32_t)(cz)), "r"((uint32_t)(mbar))      \
        : "memory")

#define LDSM4(r, addr) \
    asm volatile("ldmatrix.sync.aligned.m8n8.x4.shared.b16 {%0,%1,%2,%3}, [%4];" \
        : "=r"((r)[0]), "=r"((r)[1]), "=r"((r)[2]), "=r"((r)[3]) : "r"(addr))

#define MMA16816(c, a, b0, b1) \
    asm volatile("mma.sync.aligned.m16n8k16.row.col.f32.bf16.bf16.f32 " \
        "{%0,%1,%2,%3}, {%4,%5,%6,%7}, {%8,%9}, {%0,%1,%2,%3};" \
        : "+f"((c)[0]), "+f"((c)[1]), "+f"((c)[2]), "+f"((c)[3]) \
        : "r"((a)[0]), "r"((a)[1]), "r"((a)[2]), "r"((a)[3]), "r"(b0), "r"(b1))

// ---------------------------------------------------------------------------
// Kernel 1: LayerNorm + bf16 hi/lo split of A + fused RoPE table
//           (inv_freq precomputed on host in double; fp32 trig on device)
// ---------------------------------------------------------------------------
__global__ __launch_bounds__(256) void ln_split_kernel(
    const float* __restrict__ x,
    const float* __restrict__ gamma,
    const float* __restrict__ beta,
    const __grid_constant__ InvFreq invf)
{
    int row = blockIdx.x;

    // fused RoPE table: blocks 0..4095, threads 0..63 compute t=row's entries.
    if (row < TT_ && threadIdx.x < 64) {
        int d = threadIdx.x;
        float ang = (float)row * invf.v[d];
        float sv, cv;
        sincosf(ang, &sv, &cv);
        g_cos[row * 64 + d] = cv;
        g_sin[row * 64 + d] = sv;
    }

    const float4* xr = (const float4*)(x + (size_t)row * DD_);
    float4 v[4];
    float s = 0.f, s2 = 0.f;
#pragma unroll
    for (int i = 0; i < 4; i++) {
        v[i] = xr[threadIdx.x + i * 256];
        s  += v[i].x + v[i].y + v[i].z + v[i].w;
        s2 += v[i].x * v[i].x + v[i].y * v[i].y + v[i].z * v[i].z + v[i].w * v[i].w;
    }
    __shared__ float sh[2][8];
    int lane = threadIdx.x & 31, warp = threadIdx.x >> 5;
#pragma unroll
    for (int off = 16; off > 0; off >>= 1) {
        s  += __shfl_down_sync(0xffffffffu, s,  off);
        s2 += __shfl_down_sync(0xffffffffu, s2, off);
    }
    if (lane == 0) { sh[0][warp] = s; sh[1][warp] = s2; }
    __syncthreads();
    if (warp == 0) {
        float a  = (lane < 8) ? sh[0][lane] : 0.f;
        float b2 = (lane < 8) ? sh[1][lane] : 0.f;
#pragma unroll
        for (int off = 4; off > 0; off >>= 1) {
            a  += __shfl_down_sync(0xffffffffu, a,  off);
            b2 += __shfl_down_sync(0xffffffffu, b2, off);
        }
        if (lane == 0) { sh[0][0] = a; sh[1][0] = b2; }
    }
    __syncthreads();
    float mu  = sh[0][0] * (1.f / DD_);
    float var = sh[1][0] * (1.f / DD_) - mu * mu;
    float rs  = rsqrtf(var + 1e-5f);

    const float4* g4 = (const float4*)gamma;
    const float4* b4 = (const float4*)beta;
    __nv_bfloat16* Ahi = g_A;
    __nv_bfloat16* Alo = g_A + (size_t)MM_ * DD_;
    size_t ro = (size_t)row * DD_;
#pragma unroll
    for (int i = 0; i < 4; i++) {
        int idx = threadIdx.x + i * 256;
        float4 g = g4[idx], bt = b4[idx];
        float f[4];
        f[0] = (v[i].x - mu) * rs * g.x + bt.x;
        f[1] = (v[i].y - mu) * rs * g.y + bt.y;
        f[2] = (v[i].z - mu) * rs * g.z + bt.z;
        f[3] = (v[i].w - mu) * rs * g.w + bt.w;
        uint32_t uh[2], ul[2];
#pragma unroll
        for (int p = 0; p < 2; p++) {
            __nv_bfloat16 h0 = __float2bfloat16(f[2*p]);
            __nv_bfloat16 h1 = __float2bfloat16(f[2*p+1]);
            __nv_bfloat16 l0 = __float2bfloat16(f[2*p]   - __bfloat162float(h0));
            __nv_bfloat16 l1 = __float2bfloat16(f[2*p+1] - __bfloat162float(h1));
            uh[p] = (uint32_t)__bfloat16_as_ushort(h0) | ((uint32_t)__bfloat16_as_ushort(h1) << 16);
            ul[p] = (uint32_t)__bfloat16_as_ushort(l0) | ((uint32_t)__bfloat16_as_ushort(l1) << 16);
        }
        *(uint2*)(Ahi + ro + (size_t)idx * 4) = make_uint2(uh[0], uh[1]);
        *(uint2*)(Alo + ro + (size_t)idx * 4) = make_uint2(ul[0], ul[1]);
    }
}

// ---------------------------------------------------------------------------
// Kernel 2: weight transpose + bf16 hi/lo split (vectorized).
//           Wq|Wk|Wv [K,N] -> g_Bm [N,K].  Tile 64k x 32n per block.
// ---------------------------------------------------------------------------
__global__ __launch_bounds__(256) void wsplit_kernel(
    const float* __restrict__ Wq,
    const float* __restrict__ Wk,
    const float* __restrict__ Wv)
{
    __shared__ float tile[64][33];
    int k0 = blockIdx.x * 64, n0 = blockIdx.y * 32;
    int tid = threadIdx.x;

    const float* W; int ld, nb;
    if (n0 < NQ_)            { W = Wq; ld = NQ_;  nb = n0; }
    else if (n0 < NQ_ + NKV_){ W = Wk; ld = NKV_; nb = n0 - NQ_; }
    else                     { W = Wv; ld = NKV_; nb = n0 - NQ_ - NKV_; }

#pragma unroll
    for (int i = 0; i < 8; i++) {
        int e = tid + i * 256;          // 0..2047
        int r = e >> 5, c = e & 31;
        tile[r][c] = W[(size_t)(k0 + r) * ld + nb + c];
    }
    __syncthreads();

    __nv_bfloat16* Bhi = g_Bm;
    __nv_bfloat16* Blo = g_Bm + (size_t)NTOT_ * DD_;
    int nl = tid >> 3;                 // 0..31
    int kg = (tid & 7) * 8;            // 0,8,..,56
    uint32_t hw[4], lw[4];
#pragma unroll
    for (int p = 0; p < 4; p++) {
        float f0 = tile[kg + 2*p + 0][nl];
        float f1 = tile[kg + 2*p + 1][nl];
        __nv_bfloat16 h0 = __float2bfloat16(f0);
        __nv_bfloat16 h1 = __float2bfloat16(f1);
        __nv_bfloat16 l0 = __float2bfloat16(f0 - __bfloat162float(h0));
        __nv_bfloat16 l1 = __float2bfloat16(f1 - __bfloat162float(h1));
        hw[p] = (uint32_t)__bfloat16_as_ushort(h0) | ((uint32_t)__bfloat16_as_ushort(h1) << 16);
        lw[p] = (uint32_t)__bfloat16_as_ushort(l0) | ((uint32_t)__bfloat16_as_ushort(l1) << 16);
    }
    size_t off = (size_t)(n0 + nl) * DD_ + k0 + kg;
    *(uint4*)(Bhi + off) = make_uint4(hw[0], hw[1], hw[2], hw[3]);
    *(uint4*)(Blo + off) = make_uint4(lw[0], lw[1], lw[2], lw[3]);
}

// ---------------------------------------------------------------------------
// Kernel 3: mma.sync bf16 GEMM, CTA tile 128x128, warp tile 32x64, BK=128
//           (two 64-k slabs per stage), 3-stage TMA pipeline, tensormap
//           prefetch, early empty-arrive, fused RoPE + GQA scatter.
//           K' = 3*4096 (Ootomo 3-pass split).
// ---------------------------------------------------------------------------
#define STAGES      3
#define BK          128
#define TM          128
#define TN          128
#define KCHUNKS     32                 // 4096 / 128
#define KITERS      (3 * KCHUNKS)      // 96
#define SLAB        16384              // 128 rows x 64 k x 2B
#define A_BYTES     (2 * SLAB)         // 32768
#define B_BYTES     (2 * SLAB)         // 32768
#define STAGE_BYTES (A_BYTES + B_BYTES)  // 65536
#define SM_FULL(s)  ((s) * 16)
#define SM_EMPTY(s) ((s) * 16 + 8)
#define SM_DATA     1024
#define SMEM_TOTAL  (SM_DATA + STAGES * STAGE_BYTES)   // 197632

__global__ void __launch_bounds__(288, 1) gemm_rope_kernel(
    const __grid_constant__ CUtensorMap tmaA,
    const __grid_constant__ CUtensorMap tmaB,
    float* __restrict__ out)
{
    extern __shared__ char smem[];
    uint32_t sb = smem_u32(smem);
    const int tid = threadIdx.x, lane = tid & 31, wid = tid >> 5;
    const int n0 = blockIdx.x * TN;
    const int m0 = blockIdx.y * TM;

    // prefetch tensormap descriptors — overlaps with mbarrier init + sync
    if (wid == 8 && lane == 0) {
        TMA_PREFETCH(&tmaA);
        TMA_PREFETCH(&tmaB);
    }

    if (tid == 0) {
#pragma unroll
        for (int s = 0; s < STAGES; s++) {
            MBAR_INIT(sb + SM_FULL(s), 1);
            MBAR_INIT(sb + SM_EMPTY(s), 8);
        }
        asm volatile("fence.proxy.async.shared::cta;" ::: "memory");
    }
    __syncthreads();

    if (wid == 8) {
        // ---- producer warp ----
        if (lane == 0) {
            int s = 0, ph = 1;
            for (int it = 0; it < KITERS; it++) {
                MBAR_WAIT(sb + SM_EMPTY(s), ph);
                MBAR_EXPECT_TX(sb + SM_FULL(s), STAGE_BYTES);
                int p  = it >> 5;          // pass 0..2
                int kc = it & 31;
                int aseg = (p == 1) ? 1 : 0;
                int bseg = (p == 2) ? 1 : 0;
                uint32_t da = sb + SM_DATA + s * STAGE_BYTES;
                int kx = kc * BK;
                TMA_LOAD_3D(da,            &tmaA, kx,      m0, aseg, sb + SM_FULL(s));
                TMA_LOAD_3D(da + SLAB,     &tmaA, kx + 64, m0, aseg, sb + SM_FULL(s));
                TMA_LOAD_3D(da + 2*SLAB,   &tmaB, kx,      n0, bseg, sb + SM_FULL(s));
                TMA_LOAD_3D(da + 3*SLAB,   &tmaB, kx + 64, n0, bseg, sb + SM_FULL(s));
                if (++s == STAGES) { s = 0; ph ^= 1; }
            }
        }
        return;
    }

    // ---- compute warps 0..7: warp tile 32(M) x 64(N)
    const int g      = wid & 1;
    const int warp_m = (wid >> 1) * 32;

    float acc[2][4][2][4];
#pragma unroll
    for (int a1 = 0; a1 < 2; a1++)
#pragma unroll
        for (int a2 = 0; a2 < 4; a2++)
#pragma unroll
            for (int a3 = 0; a3 < 2; a3++)
#pragma unroll
                for (int a4 = 0; a4 < 4; a4++) acc[a1][a2][a3][a4] = 0.f;

    // lane-constant ldmatrix addressing (SW128 swizzle: kbyte ^ ((row&7)*16))
    uint32_t a_rowb[2], a_xor[2];
#pragma unroll
    for (int mt = 0; mt < 2; mt++) {
        int row = warp_m + mt * 16 + (lane & 15);
        a_rowb[mt] = row * 128;
        a_xor[mt]  = (row & 7) * 16;
    }
    const uint32_t a_kh = (lane >> 4) * 16;

    uint32_t b_rowb[4], b_xor[4];
#pragma unroll
    for (int p = 0; p < 4; p++) {
        int btile = g * 4 + p + (lane >> 4) * 8;
        int row   = btile * 8 + (lane & 7);
        b_rowb[p] = row * 128;
        b_xor[p]  = (row & 7) * 16;
    }
    const uint32_t b_kh = ((lane >> 3) & 1) * 16;

    {
        int s = 0, ph = 0;
        for (int it = 0; it < KITERS; it++) {
            MBAR_WAIT(sb + SM_FULL(s), ph);
            uint32_t base = sb + SM_DATA + s * STAGE_BYTES;
#pragma unroll
            for (int ks = 0; ks < 8; ks++) {
                uint32_t slab  = (ks >= 4) ? SLAB : 0u;
                uint32_t kb    = (ks & 3) * 32;
                uint32_t baseA = base + slab;
                uint32_t baseB = base + 2 * SLAB + slab;
                uint32_t afr[2][4], bfr[4][4];
#pragma unroll
                for (int mt = 0; mt < 2; mt++)
                    LDSM4(afr[mt], baseA + a_rowb[mt] + ((kb + a_kh) ^ a_xor[mt]));
#pragma unroll
                for (int p = 0; p < 4; p++)
                    LDSM4(bfr[p], baseB + b_rowb[p] + ((kb + b_kh) ^ b_xor[p]));
                // early empty-arrive after the final LDSM batch of the stage
                if (ks == 7 && lane == 0) MBAR_ARRIVE(sb + SM_EMPTY(s));
#pragma unroll
                for (int mt = 0; mt < 2; mt++)
#pragma unroll
                    for (int p = 0; p < 4; p++) {
                        MMA16816(acc[mt][p][0], afr[mt], bfr[p][0], bfr[p][1]);
                        MMA16816(acc[mt][p][1], afr[mt], bfr[p][2], bfr[p][3]);
                    }
            }
            if (++s == STAGES) { s = 0; ph ^= 1; }
        }
    }

    // ---- epilogue: RoPE + GQA scatter
    const long long QSZ = (long long)BB_ * HH_ * TT_ * 128;
    const int qrow  = lane >> 2;
    const int qcol2 = (lane & 3) * 2;
    const int region = (n0 < NQ_) ? 0 : ((n0 < NQ_ + NKV_) ? 1 : 2);

#pragma unroll
    for (int mt = 0; mt < 2; mt++)
#pragma unroll
        for (int rh = 0; rh < 2; rh++) {
            int m  = m0 + warp_m + mt * 16 + qrow + rh * 8;
            int b  = m >> 12, tp = m & (TT_ - 1);
#pragma unroll
            for (int p = 0; p < 4; p++) {
                int   c0  = (g * 4 + p) * 8 + qcol2;   // d in [0,64)
                float lo0 = acc[mt][p][0][rh * 2 + 0];
                float lo1 = acc[mt][p][0][rh * 2 + 1];
                float hi0 = acc[mt][p][1][rh * 2 + 0];
                float hi1 = acc[mt][p][1][rh * 2 + 1];

                if (region == 0) {
                    float2 cs = *(const float2*)&g_cos[tp * 64 + c0];
                    float2 sn = *(const float2*)&g_sin[tp * 64 + c0];
                    long long base = (((long long)(b * HH_ + (n0 >> 7))) * TT_ + tp) * 128;
                    *(float2*)&out[base + c0]      = make_float2(lo0 * cs.x - hi0 * sn.x,
                                                                 lo1 * cs.y - hi1 * sn.y);
                    *(float2*)&out[base + 64 + c0] = make_float2(hi0 * cs.x + lo0 * sn.x,
                                                                 hi1 * cs.y + lo1 * sn.y);
                } else if (region == 1) {
                    float2 cs = *(const float2*)&g_cos[tp * 64 + c0];
                    float2 sn = *(const float2*)&g_sin[tp * 64 + c0];
                    float2 o0 = make_float2(lo0 * cs.x - hi0 * sn.x,
                                            lo1 * cs.y - hi1 * sn.y);
                    float2 o1 = make_float2(hi0 * cs.x + lo0 * sn.x,
                                            hi1 * cs.y + lo1 * sn.y);
                    int kv = (n0 - NQ_) >> 7;
#pragma unroll
                    for (int e = 0; e < 4; e++) {
                        long long base = QSZ +
                            (((long long)(b * HH_ + kv * 4 + e)) * TT_ + tp) * 128;
                        *(float2*)&out[base + c0]      = o0;
                        *(float2*)&out[base + 64 + c0] = o1;
                    }
                } else {
                    int kv = (n0 - NQ_ - NKV_) >> 7;
                    float2 o0 = make_float2(lo0, lo1);
                    float2 o1 = make_float2(hi0, hi1);
#pragma unroll
                    for (int e = 0; e < 4; e++) {
                        long long base = 2 * QSZ +
                            (((long long)(b * HH_ + kv * 4 + e)) * TT_ + tp) * 128;
                        *(float2*)&out[base + c0]      = o0;
                        *(float2*)&out[base + 64 + c0] = o1;
                    }
                }
            }
        }
}

// ---------------------------------------------------------------------------
// Host launch
// ---------------------------------------------------------------------------
typedef CUresult (*PFN_encodeTiled)(
    CUtensorMap*, CUtensorMapDataType, cuuint32_t, void*,
    const cuuint64_t*, const cuuint64_t*, const cuuint32_t*, const cuuint32_t*,
    CUtensorMapInterleave, CUtensorMapSwizzle, CUtensorMapL2promotion,
    CUtensorMapFloatOOBfill);

extern "C" void kernel_launch(void* const* d_in, const int* in_sizes, int n_in,
                              void* d_out, int out_size)
{
    const float* x     = (const float*)d_in[0];
    const float* gamma = (const float*)d_in[1];
    const float* beta  = (const float*)d_in[2];
    const float* Wq    = (const float*)d_in[3];
    const float* Wk    = (const float*)d_in[4];
    const float* Wv    = (const float*)d_in[5];
    float* out = (float*)d_out;

    // host-computed inv_freq (double precision, rounded to fp32) — passed
    // by value so the graph bakes it into the launch node.
    InvFreq invf;
    for (int d = 0; d < 64; d++)
        invf.v[d] = (float)exp(-((double)(2 * d) / 128.0) * log(10000.0));

    ln_split_kernel<<<MM_, 256>>>(x, gamma, beta, invf);
    wsplit_kernel<<<dim3(DD_ / 64, NTOT_ / 32), 256>>>(Wq, Wk, Wv);

    PFN_encodeTiled encode = nullptr;
    cudaDriverEntryPointQueryResult qr;
    cudaGetDriverEntryPointByVersion("cuTensorMapEncodeTiled", (void**)&encode,
                                     12000, cudaEnableDefault, &qr);
    if (!encode) return;

    void *pa = nullptr, *pb = nullptr;
    cudaGetSymbolAddress(&pa, g_A);
    cudaGetSymbolAddress(&pb, g_Bm);

    CUtensorMap tmaA, tmaB;
    {
        cuuint64_t dims[3]    = {DD_, MM_, 2};
        cuuint64_t strides[2] = {(cuuint64_t)DD_ * 2, (cuuint64_t)MM_ * DD_ * 2};
        cuuint32_t box[3]     = {64, TM, 1};
        cuuint32_t es[3]      = {1, 1, 1};
        encode(&tmaA, CU_TENSOR_MAP_DATA_TYPE_BFLOAT16, 3, pa, dims, strides,
               box, es, CU_TENSOR_MAP_INTERLEAVE_NONE, CU_TENSOR_MAP_SWIZZLE_128B,
               CU_TENSOR_MAP_L2_PROMOTION_L2_128B, CU_TENSOR_MAP_FLOAT_OOB_FILL_NONE);
    }
    {
        cuuint64_t dims[3]    = {DD_, NTOT_, 2};
        cuuint64_t strides[2] = {(cuuint64_t)DD_ * 2, (cuuint64_t)NTOT_ * DD_ * 2};
        cuuint32_t box[3]     = {64, TN, 1};
        cuuint32_t es[3]      = {1, 1, 1};
        encode(&tmaB, CU_TENSOR_MAP_DATA_TYPE_BFLOAT16, 3, pb, dims, strides,
               box, es, CU_TENSOR_MAP_INTERLEAVE_NONE, CU_TENSOR_MAP_SWIZZLE_128B,
               CU_TENSOR_MAP_L2_PROMOTION_L2_128B, CU_TENSOR_MAP_FLOAT_OOB_FILL_NONE);
    }

    cudaFuncSetAttribute(gemm_rope_kernel,
                         cudaFuncAttributeMaxDynamicSharedMemorySize, SMEM_TOTAL);
    dim3 grid(NTOT_ / TN, MM_ / TM);   // 48 x 64
    gemm_rope_kernel<<<grid, 288, SMEM_TOTAL>>>(tmaA, tmaB, out);
}